// round 11
// baseline (speedup 1.0000x reference)
#include <cuda_runtime.h>

// SSIM loss — single fused kernel.
// d_in[0] = sr_image (16,3,512,512) f32, d_in[1] = hr_image (16,3,512,512) f32.
// Only channel 0 used. Output: 1 float = mean SSIM over (16,1,502,502).

#define IMG     512
#define OUT_DIM 502
#define TX      32
#define TY      32
#define INX     42          // TX + 10
#define INY     42          // TY + 10
#define ST_AB   43          // 64-bit-word row stride for input tile (odd -> conflict-free)
#define ST_T    33          // row stride for intermediates (odd)
#define NBX     16
#define NBY     16
#define NIMG    16
#define NBLK    (NBX * NBY * NIMG)

__device__ float        g_part[NBLK];
__device__ unsigned int g_count = 0;

// ---- packed f32x2 helpers (Blackwell fma.rn.f32x2 path) ----
typedef unsigned long long ull;

static __device__ __forceinline__ ull pk2(float x, float y) {
    ull r; asm("mov.b64 %0, {%1, %2};" : "=l"(r) : "f"(x), "f"(y)); return r;
}
static __device__ __forceinline__ void upk2(ull v, float& x, float& y) {
    asm("mov.b64 {%0, %1}, %2;" : "=f"(x), "=f"(y) : "l"(v));
}
static __device__ __forceinline__ ull fma2(ull a, ull b, ull c) {
    ull d; asm("fma.rn.f32x2 %0, %1, %2, %3;" : "=l"(d) : "l"(a), "l"(b), "l"(c)); return d;
}
static __device__ __forceinline__ ull mul2(ull a, ull b) {
    ull d; asm("mul.rn.f32x2 %0, %1, %2;" : "=l"(d) : "l"(a), "l"(b)); return d;
}

// 1D Gaussian (sigma=1.5, size=11), normalized; outer product == fspecial_gauss.
__host__ __device__ __forceinline__ constexpr float Wk(int k) {
    constexpr float W[11] = {
        0.001028380f, 0.007598758f, 0.036000773f, 0.109360702f, 0.213005529f,
        0.266011716f,
        0.213005529f, 0.109360702f, 0.036000773f, 0.007598758f, 0.001028380f
    };
    return (k >= 0 && k < 11) ? W[k] : 0.0f;
}

// Pre-packed 64-bit weight words in __constant__ memory (bit-exact packing).
// Lets ptxas use the LDCU->UR path instead of re-materializing mov.b64 pairs.
static constexpr ull mkpair(float lo, float hi) {
    return (ull)__builtin_bit_cast(unsigned int, lo)
         | ((ull)__builtin_bit_cast(unsigned int, hi) << 32);
}
#define WB_(k)  mkpair(Wk(k), Wk(k))
#define WP_(k)  mkpair(Wk(k), Wk((k) - 1))
__constant__ ull c_wb[11] = {
    WB_(0), WB_(1), WB_(2), WB_(3), WB_(4), WB_(5),
    WB_(6), WB_(7), WB_(8), WB_(9), WB_(10)
};
__constant__ ull c_wp[12] = {            // (W[k0], W[k0-1]) for xy column pairs
    WP_(0), WP_(1), WP_(2), WP_(3), WP_(4), WP_(5),
    WP_(6), WP_(7), WP_(8), WP_(9), WP_(10), WP_(11)
};

__global__ __launch_bounds__(256, 5)
void ssim_kernel(const float* __restrict__ sr, const float* __restrict__ hr,
                 float* __restrict__ out)
{
    __shared__ ull        s_ab[INY * ST_AB + 8];  // (hr,sr) packed (+pad: last-seg overrun)
    __shared__ ulonglong2 s_q [INY * ST_T];       // {(mu1,mu2),(Ex2,Ey2)} packed 16B
    __shared__ float      s_xy[INY * ST_T];       // horiz E[xy]
    __shared__ float      s_wsum[8];
    __shared__ double     s_dred[8];
    __shared__ int        s_last;

    const int tid = threadIdx.x;
    const int bx  = blockIdx.x, by = blockIdx.y, bz = blockIdx.z;
    const int oy0 = by * TY;
    const int ox0 = bx * TX;
    const size_t img_base = (size_t)bz * 3 * IMG * IMG;   // channel 0
    const float* __restrict__ A = hr + img_base;
    const float* __restrict__ B = sr + img_base;

    // ---------------- Phase 1: stage 42x42 (a,b) tile packed as 64-bit words ---
    #pragma unroll
    for (int it = 0; it < 7; it++) {
        int idx = tid + it * 256;
        if (idx < INY * INX) {
            int r = idx / INX;
            int c = idx - r * INX;
            int gy = oy0 + r, gx = ox0 + c;
            float a = 0.f, b = 0.f;
            if (gy < IMG && gx < IMG) {
                int g = gy * IMG + gx;
                a = A[g];
                b = B[g];
            }
            s_ab[r * ST_AB + c] = pk2(a, b);
        }
    }
    __syncthreads();

    // ---------------- Phase 2: horizontal pass, 6-wide sliding window ----------
    // 6 segments x 6 cols (cols 32..35 computed, discarded) x 42 rows = 252 items.
    if (tid < 252) {
        int seg = tid / INY;           // 0..5
        int row = tid - seg * INY;     // 0..41
        int c0  = seg * 6;
        const ull* p = &s_ab[row * ST_AB + c0];

        ull mm[6]  = {0, 0, 0, 0, 0, 0};
        ull ss[6]  = {0, 0, 0, 0, 0, 0};
        ull xyp[3] = {0, 0, 0};        // lanes: (xy0,xy1) (xy2,xy3) (xy4,xy5)

        #pragma unroll
        for (int e = 0; e < 16; e++) {
            ull pv = p[e];                       // LDS.64 -> aligned pair
            ull sq = mul2(pv, pv);
            float a, b; upk2(pv, a, b);
            float ab = a * b;
            ull abp = pk2(ab, ab);
            #pragma unroll
            for (int j = 0; j < 6; j++) {
                int k = e - j;                   // compile-time resolved
                if (k >= 0 && k < 11) {
                    ull ww = c_wb[k];            // LDCU/UR, hoisted by ptxas
                    mm[j] = fma2(ww, pv, mm[j]);
                    ss[j] = fma2(ww, sq, ss[j]);
                }
            }
            #pragma unroll
            for (int jp = 0; jp < 3; jp++) {
                int k0 = e - 2 * jp;             // weight for lane0 (col 2jp)
                if (k0 >= 0 && k0 < 12) {        // lane1 uses k0-1
                    ull wp = c_wp[k0];
                    xyp[jp] = fma2(wp, abp, xyp[jp]);
                }
            }
        }
        #pragma unroll
        for (int j = 0; j < 6; j++) {
            int col = c0 + j;
            if (col < TX) {
                int o = row * ST_T + col;
                s_q[o] = make_ulonglong2(mm[j], ss[j]);   // STS.128
                float x0, x1; upk2(xyp[j >> 1], x0, x1);
                s_xy[o] = (j & 1) ? x1 : x0;
            }
        }
    }
    __syncthreads();

    // ---------------- Phase 3: vertical pass, 4 output rows per thread ---------
    const int c  = tid & 31;           // column
    const int r0 = (tid >> 5) * 4;     // first output row of this thread

    const ulonglong2* pq  = &s_q [r0 * ST_T + c];
    const float*      pxy = &s_xy[r0 * ST_T + c];

    ull vm[4]  = {0, 0, 0, 0};
    ull vs[4]  = {0, 0, 0, 0};
    ull vxp[2] = {0, 0};               // lanes: (vx0,vx1) (vx2,vx3)

    #pragma unroll
    for (int e = 0; e < 14; e++) {
        ulonglong2 q = pq [e * ST_T]; // LDS.128: (mu1,mu2),(Ex2,Ey2)
        float      x = pxy[e * ST_T];
        ull xp = pk2(x, x);
        #pragma unroll
        for (int j = 0; j < 4; j++) {
            int k = e - j;
            if (k >= 0 && k < 11) {
                ull ww = c_wb[k];
                vm[j] = fma2(ww, q.x, vm[j]);
                vs[j] = fma2(ww, q.y, vs[j]);
            }
        }
        #pragma unroll
        for (int jp = 0; jp < 2; jp++) {
            int k0 = e - 2 * jp;
            if (k0 >= 0 && k0 < 12) {
                ull wp = c_wp[k0];
                vxp[jp] = fma2(wp, xp, vxp[jp]);
            }
        }
    }

    // ---------------- SSIM formula + accumulate --------------------------------
    const float C1 = 1e-4f;   // (0.01*1)^2
    const float C2 = 9e-4f;   // (0.03*1)^2
    float vx[4];
    upk2(vxp[0], vx[0], vx[1]);
    upk2(vxp[1], vx[2], vx[3]);

    float local = 0.f;
    #pragma unroll
    for (int j = 0; j < 4; j++) {
        int gy = oy0 + r0 + j;
        int gx = ox0 + c;
        if (gy < OUT_DIM && gx < OUT_DIM) {
            float mu1, mu2, ex2, ey2;
            upk2(vm[j], mu1, mu2);
            upk2(vs[j], ex2, ey2);
            float mu1s = mu1 * mu1;
            float mu2s = mu2 * mu2;
            float mu12 = mu1 * mu2;
            float sig1 = ex2 - mu1s;
            float sig2 = ey2 - mu2s;
            float s12  = vx[j] - mu12;
            float num  = (2.f * mu12 + C1) * (2.f * s12 + C2);
            float den  = (mu1s + mu2s + C1) * (sig1 + sig2 + C2);
            local += __fdividef(num, den);
        }
    }

    // block reduction
    #pragma unroll
    for (int off = 16; off > 0; off >>= 1)
        local += __shfl_down_sync(0xffffffffu, local, off);
    if ((tid & 31) == 0)
        s_wsum[tid >> 5] = local;
    __syncthreads();

    const int bid = bx + NBX * (by + NBY * bz);
    if (tid == 0) {
        float t = 0.f;
        #pragma unroll
        for (int i = 0; i < 8; i++) t += s_wsum[i];
        g_part[bid] = t;
        __threadfence();
        unsigned old = atomicInc(&g_count, NBLK - 1);   // wraps to 0 on last
        s_last = (old == NBLK - 1);
    }
    __syncthreads();

    // ---------------- Last block: deterministic final reduce -------------------
    if (s_last) {
        double d = 0.0;
        for (int i = tid; i < NBLK; i += 256)
            d += (double)__ldcg(&g_part[i]);
        #pragma unroll
        for (int off = 16; off > 0; off >>= 1)
            d += __shfl_down_sync(0xffffffffu, d, off);
        if ((tid & 31) == 0)
            s_dred[tid >> 5] = d;
        __syncthreads();
        if (tid == 0) {
            double s = 0.0;
            #pragma unroll
            for (int i = 0; i < 8; i++) s += s_dred[i];
            out[0] = (float)(s / ((double)NIMG * OUT_DIM * OUT_DIM));
        }
    }
}

extern "C" void kernel_launch(void* const* d_in, const int* in_sizes, int n_in,
                              void* d_out, int out_size)
{
    const float* sr = (const float*)d_in[0];
    const float* hr = (const float*)d_in[1];
    dim3 grid(NBX, NBY, NIMG);
    ssim_kernel<<<grid, 256>>>(sr, hr, (float*)d_out);
}

// round 14
// speedup vs baseline: 1.1174x; 1.1174x over previous
#include <cuda_runtime.h>

// SSIM loss — single fused kernel, 4-quantity formulation.
// d_in[0] = sr_image (16,3,512,512) f32, d_in[1] = hr_image (16,3,512,512) f32.
// Only channel 0 used. Output: 1 float = mean SSIM over (16,1,502,502).
//
// Algebra: with t = a+b,  E[a^2]+E[b^2] = E[t^2] - 2 E[ab], so SSIM needs only
// conv of {a, b, ab, t^2}  (sigma1^2+sigma2^2 = E[t^2]-2E[ab]-mu1^2-mu2^2).

#define IMG     512
#define OUT_DIM 502
#define TX      32
#define TY      32
#define INX     42          // TX + 10
#define INY     42          // TY + 10
#define ST_AB   43          // 64-bit-word row stride for input tile (odd -> conflict-free)
#define ST_T    33          // row stride for intermediates (odd)
#define NBX     16
#define NBY     16
#define NIMG    16
#define NBLK    (NBX * NBY * NIMG)

__device__ float        g_part[NBLK];
__device__ unsigned int g_count = 0;

// ---- packed f32x2 helpers (Blackwell fma.rn.f32x2 path) ----
typedef unsigned long long ull;

static __device__ __forceinline__ ull pk2(float x, float y) {
    ull r; asm("mov.b64 %0, {%1, %2};" : "=l"(r) : "f"(x), "f"(y)); return r;
}
static __device__ __forceinline__ void upk2(ull v, float& x, float& y) {
    asm("mov.b64 {%0, %1}, %2;" : "=f"(x), "=f"(y) : "l"(v));
}
static __device__ __forceinline__ ull fma2(ull a, ull b, ull c) {
    ull d; asm("fma.rn.f32x2 %0, %1, %2, %3;" : "=l"(d) : "l"(a), "l"(b), "l"(c)); return d;
}
static __device__ __forceinline__ ull mul2(ull a, ull b) {
    ull d; asm("mul.rn.f32x2 %0, %1, %2;" : "=l"(d) : "l"(a), "l"(b)); return d;
}

// 1D Gaussian (sigma=1.5, size=11), normalized; outer product == fspecial_gauss.
__host__ __device__ __forceinline__ constexpr float Wk(int k) {
    constexpr float W[11] = {
        0.001028380f, 0.007598758f, 0.036000773f, 0.109360702f, 0.213005529f,
        0.266011716f,
        0.213005529f, 0.109360702f, 0.036000773f, 0.007598758f, 0.001028380f
    };
    return (k >= 0 && k < 11) ? W[k] : 0.0f;
}

__global__ __launch_bounds__(256, 5)
void ssim_kernel(const float* __restrict__ sr, const float* __restrict__ hr,
                 float* __restrict__ out)
{
    __shared__ ull        s_ab[INY * ST_AB + 8];  // (a,b) packed (+pad: last-seg overrun)
    __shared__ ulonglong2 s_q [INY * ST_T];       // {(mu1,mu2),(E[ab],E[t^2])} packed 16B
    __shared__ float      s_wsum[8];
    __shared__ double     s_dred[8];
    __shared__ int        s_last;

    const int tid = threadIdx.x;
    const int bx  = blockIdx.x, by = blockIdx.y, bz = blockIdx.z;
    const int oy0 = by * TY;
    const int ox0 = bx * TX;
    const size_t img_base = (size_t)bz * 3 * IMG * IMG;   // channel 0
    const float* __restrict__ A = hr + img_base;
    const float* __restrict__ B = sr + img_base;

    // ---------------- Phase 1: stage 42x42 (a,b) tile, float2 loads, no div ----
    {
        const int w = tid >> 5;        // 0..7
        const int l = tid & 31;        // lane
        if (l < 21) {                  // 21 float2-columns cover cols 0..41
            const int gx = ox0 + 2 * l;        // even; gx <= 520
            #pragma unroll
            for (int k = 0; k < 6; k++) {
                int r = w + 8 * k;             // rows 0..41 (+idle for r>=42)
                if (r < INY) {
                    int gy = oy0 + r;
                    float2 av = make_float2(0.f, 0.f);
                    float2 bv = make_float2(0.f, 0.f);
                    if (gy < IMG && gx < IMG) {        // gx even => gx+1 <= 511 too
                        const float* pa = A + gy * IMG + gx;
                        const float* pb = B + gy * IMG + gx;
                        av = *reinterpret_cast<const float2*>(pa);
                        bv = *reinterpret_cast<const float2*>(pb);
                    }
                    s_ab[r * ST_AB + 2 * l]     = pk2(av.x, bv.x);
                    s_ab[r * ST_AB + 2 * l + 1] = pk2(av.y, bv.y);
                }
            }
        }
    }
    __syncthreads();

    // ---------------- Phase 2: horizontal pass, 6-wide sliding window ----------
    // 6 segments x 6 cols (cols 32..35 computed, discarded) x 42 rows = 252 items.
    if (tid < 252) {
        int seg = tid / INY;           // 0..5
        int row = tid - seg * INY;     // 0..41
        int c0  = seg * 6;
        const ull* p = &s_ab[row * ST_AB + c0];

        ull mm[6] = {0, 0, 0, 0, 0, 0};   // (mu1, mu2)
        ull uu[6] = {0, 0, 0, 0, 0, 0};   // (E[ab], E[t^2])

        #pragma unroll
        for (int e = 0; e < 16; e++) {
            ull pv = p[e];                       // LDS.64 -> aligned pair (a,b)
            float a, b; upk2(pv, a, b);
            float t = a + b;
            ull u = mul2(pk2(a, t), pk2(b, t));  // (a*b, t*t)
            #pragma unroll
            for (int j = 0; j < 6; j++) {
                int k = e - j;                   // compile-time resolved
                if (k >= 0 && k < 11) {
                    ull ww = pk2(Wk(k), Wk(k));
                    mm[j] = fma2(ww, pv, mm[j]);
                    uu[j] = fma2(ww, u,  uu[j]);
                }
            }
        }
        #pragma unroll
        for (int j = 0; j < 6; j++) {
            int col = c0 + j;
            if (col < TX) {
                s_q[row * ST_T + col] = make_ulonglong2(mm[j], uu[j]);  // STS.128
            }
        }
    }
    __syncthreads();

    // ---------------- Phase 3: vertical pass, 4 output rows per thread ---------
    const int c  = tid & 31;           // column
    const int r0 = (tid >> 5) * 4;     // first output row of this thread

    const ulonglong2* pq = &s_q[r0 * ST_T + c];

    ull vm[4] = {0, 0, 0, 0};          // (mu1, mu2)
    ull vu[4] = {0, 0, 0, 0};          // (E[ab], E[t^2])

    #pragma unroll
    for (int e = 0; e < 14; e++) {
        ulonglong2 q = pq[e * ST_T];   // LDS.128
        #pragma unroll
        for (int j = 0; j < 4; j++) {
            int k = e - j;
            if (k >= 0 && k < 11) {
                ull ww = pk2(Wk(k), Wk(k));
                vm[j] = fma2(ww, q.x, vm[j]);
                vu[j] = fma2(ww, q.y, vu[j]);
            }
        }
    }

    // ---------------- SSIM formula + accumulate --------------------------------
    const float C1 = 1e-4f;   // (0.01*1)^2
    const float C2 = 9e-4f;   // (0.03*1)^2
    float local = 0.f;
    #pragma unroll
    for (int j = 0; j < 4; j++) {
        int gy = oy0 + r0 + j;
        int gx = ox0 + c;
        if (gy < OUT_DIM && gx < OUT_DIM) {
            float mu1, mu2, eab, et2;
            upk2(vm[j], mu1, mu2);
            upk2(vu[j], eab, et2);
            float mu1s   = mu1 * mu1;
            float mu2s   = mu2 * mu2;
            float mu12   = mu1 * mu2;
            float musum  = mu1s + mu2s;
            float s12    = eab - mu12;                    // sigma12
            float sigsum = et2 - 2.f * eab - musum;       // sigma1^2 + sigma2^2
            float num    = (2.f * mu12 + C1) * (2.f * s12 + C2);
            float den    = (musum + C1) * (sigsum + C2);
            local += __fdividef(num, den);
        }
    }

    // block reduction
    #pragma unroll
    for (int off = 16; off > 0; off >>= 1)
        local += __shfl_down_sync(0xffffffffu, local, off);
    if ((tid & 31) == 0)
        s_wsum[tid >> 5] = local;
    __syncthreads();

    const int bid = bx + NBX * (by + NBY * bz);
    if (tid == 0) {
        float t = 0.f;
        #pragma unroll
        for (int i = 0; i < 8; i++) t += s_wsum[i];
        g_part[bid] = t;
        __threadfence();
        unsigned old = atomicInc(&g_count, NBLK - 1);   // wraps to 0 on last
        s_last = (old == NBLK - 1);
    }
    __syncthreads();

    // ---------------- Last block: deterministic final reduce -------------------
    if (s_last) {
        double d = 0.0;
        for (int i = tid; i < NBLK; i += 256)
            d += (double)__ldcg(&g_part[i]);
        #pragma unroll
        for (int off = 16; off > 0; off >>= 1)
            d += __shfl_down_sync(0xffffffffu, d, off);
        if ((tid & 31) == 0)
            s_dred[tid >> 5] = d;
        __syncthreads();
        if (tid == 0) {
            double s = 0.0;
            #pragma unroll
            for (int i = 0; i < 8; i++) s += s_dred[i];
            out[0] = (float)(s / ((double)NIMG * OUT_DIM * OUT_DIM));
        }
    }
}

extern "C" void kernel_launch(void* const* d_in, const int* in_sizes, int n_in,
                              void* d_out, int out_size)
{
    const float* sr = (const float*)d_in[0];
    const float* hr = (const float*)d_in[1];
    dim3 grid(NBX, NBY, NIMG);
    ssim_kernel<<<grid, 256>>>(sr, hr, (float*)d_out);
}

// round 15
// speedup vs baseline: 1.1737x; 1.0504x over previous
#include <cuda_runtime.h>

// SSIM loss — single fused kernel, 4-quantity formulation.
// d_in[0] = sr_image (16,3,512,512) f32, d_in[1] = hr_image (16,3,512,512) f32.
// Only channel 0 used. Output: 1 float = mean SSIM over (16,1,502,502).
//
// Algebra: with t = a+b,  E[a^2]+E[b^2] = E[t^2] - 2 E[ab], so SSIM needs only
// conv of {a, b, ab, t^2}  (sigma1^2+sigma2^2 = E[t^2]-2E[ab]-mu1^2-mu2^2).

#define IMG     512
#define OUT_DIM 502
#define TX      32
#define TY      32
#define INX     42          // TX + 10
#define INY     42          // TY + 10
#define ST_AB   43          // 64-bit-word row stride for input tile (odd -> conflict-free)
#define ST_T    33          // row stride for intermediates (odd)
#define NBX     16
#define NBY     16
#define NIMG    16
#define NBLK    (NBX * NBY * NIMG)

__device__ float        g_part[NBLK];
__device__ unsigned int g_count = 0;

// ---- packed f32x2 helpers (Blackwell fma.rn.f32x2 path) ----
typedef unsigned long long ull;

static __device__ __forceinline__ ull pk2(float x, float y) {
    ull r; asm("mov.b64 %0, {%1, %2};" : "=l"(r) : "f"(x), "f"(y)); return r;
}
static __device__ __forceinline__ void upk2(ull v, float& x, float& y) {
    asm("mov.b64 {%0, %1}, %2;" : "=f"(x), "=f"(y) : "l"(v));
}
static __device__ __forceinline__ ull fma2(ull a, ull b, ull c) {
    ull d; asm("fma.rn.f32x2 %0, %1, %2, %3;" : "=l"(d) : "l"(a), "l"(b), "l"(c)); return d;
}
static __device__ __forceinline__ ull mul2(ull a, ull b) {
    ull d; asm("mul.rn.f32x2 %0, %1, %2;" : "=l"(d) : "l"(a), "l"(b)); return d;
}

// 1D Gaussian (sigma=1.5, size=11), normalized; outer product == fspecial_gauss.
__host__ __device__ __forceinline__ constexpr float Wk(int k) {
    constexpr float W[11] = {
        0.001028380f, 0.007598758f, 0.036000773f, 0.109360702f, 0.213005529f,
        0.266011716f,
        0.213005529f, 0.109360702f, 0.036000773f, 0.007598758f, 0.001028380f
    };
    return (k >= 0 && k < 11) ? W[k] : 0.0f;
}

__global__ __launch_bounds__(256, 6)
void ssim_kernel(const float* __restrict__ sr, const float* __restrict__ hr,
                 float* __restrict__ out)
{
    __shared__ ull        s_ab[INY * ST_AB + 8];  // (a,b) packed (+pad: last-seg overrun)
    __shared__ ulonglong2 s_q [INY * ST_T];       // {(mu1,mu2),(E[ab],E[t^2])} packed 16B
    __shared__ float      s_wsum[8];
    __shared__ double     s_dred[8];
    __shared__ int        s_last;

    const int tid = threadIdx.x;
    const int bx  = blockIdx.x, by = blockIdx.y, bz = blockIdx.z;
    const int oy0 = by * TY;
    const int ox0 = bx * TX;
    const size_t img_base = (size_t)bz * 3 * IMG * IMG;   // channel 0
    const float* __restrict__ A = hr + img_base;
    const float* __restrict__ B = sr + img_base;

    // ---------------- Phase 1: stage 42x42 (a,b) tile, float2 loads, no div ----
    {
        const int w = tid >> 5;        // 0..7
        const int l = tid & 31;        // lane
        if (l < 21) {                  // 21 float2-columns cover cols 0..41
            const int gx = ox0 + 2 * l;        // even; gx <= 520
            #pragma unroll
            for (int k = 0; k < 6; k++) {
                int r = w + 8 * k;             // rows 0..41 (+idle for r>=42)
                if (r < INY) {
                    int gy = oy0 + r;
                    float2 av = make_float2(0.f, 0.f);
                    float2 bv = make_float2(0.f, 0.f);
                    if (gy < IMG && gx < IMG) {        // gx even => gx+1 <= 511 too
                        const float* pa = A + gy * IMG + gx;
                        const float* pb = B + gy * IMG + gx;
                        av = *reinterpret_cast<const float2*>(pa);
                        bv = *reinterpret_cast<const float2*>(pb);
                    }
                    s_ab[r * ST_AB + 2 * l]     = pk2(av.x, bv.x);
                    s_ab[r * ST_AB + 2 * l + 1] = pk2(av.y, bv.y);
                }
            }
        }
    }
    __syncthreads();

    // ---------------- Phase 2: horizontal pass, 6-wide sliding window ----------
    // 6 segments x 6 cols (cols 32..35 computed, discarded) x 42 rows = 252 items.
    if (tid < 252) {
        int seg = tid / INY;           // 0..5
        int row = tid - seg * INY;     // 0..41
        int c0  = seg * 6;
        const ull* p = &s_ab[row * ST_AB + c0];

        ull mm[6] = {0, 0, 0, 0, 0, 0};   // (mu1, mu2)
        ull uu[6] = {0, 0, 0, 0, 0, 0};   // (E[ab], E[t^2])

        #pragma unroll
        for (int e = 0; e < 16; e++) {
            ull pv = p[e];                       // LDS.64 -> aligned pair (a,b)
            float a, b; upk2(pv, a, b);
            float t = a + b;
            ull u = mul2(pk2(a, t), pk2(b, t));  // (a*b, t*t)
            #pragma unroll
            for (int j = 0; j < 6; j++) {
                int k = e - j;                   // compile-time resolved
                if (k >= 0 && k < 11) {
                    ull ww = pk2(Wk(k), Wk(k));
                    mm[j] = fma2(ww, pv, mm[j]);
                    uu[j] = fma2(ww, u,  uu[j]);
                }
            }
        }
        #pragma unroll
        for (int j = 0; j < 6; j++) {
            int col = c0 + j;
            if (col < TX) {
                s_q[row * ST_T + col] = make_ulonglong2(mm[j], uu[j]);  // STS.128
            }
        }
    }
    __syncthreads();

    // ---------------- Phase 3: vertical pass, 4 output rows per thread ---------
    const int c  = tid & 31;           // column
    const int r0 = (tid >> 5) * 4;     // first output row of this thread

    const ulonglong2* pq = &s_q[r0 * ST_T + c];

    ull vm[4] = {0, 0, 0, 0};          // (mu1, mu2)
    ull vu[4] = {0, 0, 0, 0};          // (E[ab], E[t^2])

    #pragma unroll
    for (int e = 0; e < 14; e++) {
        ulonglong2 q = pq[e * ST_T];   // LDS.128
        #pragma unroll
        for (int j = 0; j < 4; j++) {
            int k = e - j;
            if (k >= 0 && k < 11) {
                ull ww = pk2(Wk(k), Wk(k));
                vm[j] = fma2(ww, q.x, vm[j]);
                vu[j] = fma2(ww, q.y, vu[j]);
            }
        }
    }

    // ---------------- SSIM formula + accumulate --------------------------------
    const float C1 = 1e-4f;   // (0.01*1)^2
    const float C2 = 9e-4f;   // (0.03*1)^2
    float local = 0.f;
    #pragma unroll
    for (int j = 0; j < 4; j++) {
        int gy = oy0 + r0 + j;
        int gx = ox0 + c;
        if (gy < OUT_DIM && gx < OUT_DIM) {
            float mu1, mu2, eab, et2;
            upk2(vm[j], mu1, mu2);
            upk2(vu[j], eab, et2);
            float mu1s   = mu1 * mu1;
            float mu2s   = mu2 * mu2;
            float mu12   = mu1 * mu2;
            float musum  = mu1s + mu2s;
            float s12    = eab - mu12;                    // sigma12
            float sigsum = et2 - 2.f * eab - musum;       // sigma1^2 + sigma2^2
            float num    = (2.f * mu12 + C1) * (2.f * s12 + C2);
            float den    = (musum + C1) * (sigsum + C2);
            local += __fdividef(num, den);
        }
    }

    // block reduction
    #pragma unroll
    for (int off = 16; off > 0; off >>= 1)
        local += __shfl_down_sync(0xffffffffu, local, off);
    if ((tid & 31) == 0)
        s_wsum[tid >> 5] = local;
    __syncthreads();

    const int bid = bx + NBX * (by + NBY * bz);
    if (tid == 0) {
        float t = 0.f;
        #pragma unroll
        for (int i = 0; i < 8; i++) t += s_wsum[i];
        g_part[bid] = t;
        __threadfence();
        unsigned old = atomicInc(&g_count, NBLK - 1);   // wraps to 0 on last
        s_last = (old == NBLK - 1);
    }
    __syncthreads();

    // ---------------- Last block: deterministic final reduce -------------------
    if (s_last) {
        double d = 0.0;
        for (int i = tid; i < NBLK; i += 256)
            d += (double)__ldcg(&g_part[i]);
        #pragma unroll
        for (int off = 16; off > 0; off >>= 1)
            d += __shfl_down_sync(0xffffffffu, d, off);
        if ((tid & 31) == 0)
            s_dred[tid >> 5] = d;
        __syncthreads();
        if (tid == 0) {
            double s = 0.0;
            #pragma unroll
            for (int i = 0; i < 8; i++) s += s_dred[i];
            out[0] = (float)(s / ((double)NIMG * OUT_DIM * OUT_DIM));
        }
    }
}

extern "C" void kernel_launch(void* const* d_in, const int* in_sizes, int n_in,
                              void* d_out, int out_size)
{
    const float* sr = (const float*)d_in[0];
    const float* hr = (const float*)d_in[1];
    dim3 grid(NBX, NBY, NIMG);
    ssim_kernel<<<grid, 256>>>(sr, hr, (float*)d_out);
}